// round 13
// baseline (speedup 1.0000x reference)
#include <cuda_runtime.h>
#include <cuda.h>
#include <cuda_bf16.h>
#include <math.h>
#include <stdint.h>

#define Bb 256
#define Dd 2048
#define Nn 65536
#define Pp 4096
#define CTOT (Pp + Nn)
#define TINV 20.0f
#define EPS_ 0.1f

#define BMg 128                  // M rows per CTA
#define BNg 128                  // N cols per CTA
#define NBLK (Nn / BNg)          // 512 N-blocks
#define KC 32                    // K elems per stage
#define NIT (Dd / KC)            // 64 stages
#define NSTG 4
#define A_BY 8192                // A bf16: 128 rows x 64 B (SW64)
#define BB_BY 8192               // B bf16: 128 rows x 64 B (SW64-style)
#define STG_BY (A_BY + BB_BY)    // 16384
#define SMEM_DYN (NSTG * STG_BY + 1024)   // 66560

__device__ __align__(128) float g_xn[Bb * Dd];
__device__ __align__(128) __nv_bfloat16 g_xnb[Bb * Dd];
__device__ float g_M[Bb], g_szp[Bb], g_sep[Bb], g_zt[Bb], g_rowloss[Bb];
__device__ float g_psv[Bb * NBLK], g_pse[Bb * NBLK];

// ---------------- PTX helpers ----------------
__device__ __forceinline__ uint32_t cvs(const void* p) {
    return (uint32_t)__cvta_generic_to_shared(p);
}
__device__ __forceinline__ void mbar_init(uint32_t a, uint32_t c) {
    asm volatile("mbarrier.init.shared.b64 [%0], %1;" :: "r"(a), "r"(c) : "memory");
}
__device__ __forceinline__ void mbar_expect(uint32_t a, uint32_t tx) {
    asm volatile("mbarrier.arrive.expect_tx.shared.b64 _, [%0], %1;"
                 :: "r"(a), "r"(tx) : "memory");
}
__device__ __forceinline__ void mbar_wait(uint32_t a, uint32_t ph) {
    asm volatile(
        "{\n\t.reg .pred P;\n\t"
        "W_%=:\n\t"
        "mbarrier.try_wait.parity.acquire.cta.shared::cta.b64 P, [%0], %1, 0x989680;\n\t"
        "@P bra D_%=;\n\t"
        "bra.uni W_%=;\n\t"
        "D_%=:\n\t}"
        :: "r"(a), "r"(ph) : "memory");
}
__device__ __forceinline__ void tma2d(uint32_t dst, const CUtensorMap* m,
                                      int x, int y, uint32_t bar) {
    asm volatile(
        "cp.async.bulk.tensor.2d.shared::cta.global.tile.mbarrier::complete_tx::bytes "
        "[%0], [%1, {%2, %3}], [%4];"
        :: "r"(dst), "l"(m), "r"(x), "r"(y), "r"(bar) : "memory");
}
__device__ __forceinline__ void ldsm4(uint32_t& r0, uint32_t& r1, uint32_t& r2,
                                      uint32_t& r3, uint32_t addr) {
    asm volatile(
        "ldmatrix.sync.aligned.m8n8.x4.shared.b16 {%0,%1,%2,%3}, [%4];"
        : "=r"(r0), "=r"(r1), "=r"(r2), "=r"(r3) : "r"(addr));
}
__device__ __forceinline__ void mma16(float c[4], const uint32_t a[4],
                                      uint32_t b0, uint32_t b1) {
    asm("mma.sync.aligned.m16n8k16.row.col.f32.bf16.bf16.f32 "
        "{%0,%1,%2,%3},{%4,%5,%6,%7},{%8,%9},{%0,%1,%2,%3};"
        : "+f"(c[0]), "+f"(c[1]), "+f"(c[2]), "+f"(c[3])
        : "r"(a[0]), "r"(a[1]), "r"(a[2]), "r"(a[3]), "r"(b0), "r"(b1));
}
__device__ __forceinline__ uint32_t pack2(float a, float b) {
    __nv_bfloat162 p = __floats2bfloat162_rn(a, b);
    return *(uint32_t*)&p;
}

// ---------------- K1: normalize inputs (fp32 + bf16 out) ----------------
__global__ void k_normalize(const float* __restrict__ in) {
    int row = blockIdx.x, tid = threadIdx.x;
    const float4* src = (const float4*)(in + (size_t)row * Dd);
    float4 v0 = src[tid], v1 = src[tid + 256];
    float ss = v0.x*v0.x + v0.y*v0.y + v0.z*v0.z + v0.w*v0.w
             + v1.x*v1.x + v1.y*v1.y + v1.z*v1.z + v1.w*v1.w;
    #pragma unroll
    for (int o = 16; o; o >>= 1) ss += __shfl_xor_sync(~0u, ss, o);
    __shared__ float sh[8];
    if ((tid & 31) == 0) sh[tid >> 5] = ss;
    __syncthreads();
    if (tid == 0) {
        float t = 0.f;
        #pragma unroll
        for (int i = 0; i < 8; i++) t += sh[i];
        sh[0] = rsqrtf(t);
    }
    __syncthreads();
    float iv = sh[0];
    v0.x*=iv; v0.y*=iv; v0.z*=iv; v0.w*=iv;
    v1.x*=iv; v1.y*=iv; v1.z*=iv; v1.w*=iv;
    float4* dst = (float4*)(g_xn + (size_t)row * Dd);
    dst[tid] = v0; dst[tid + 256] = v1;
    uint2* bdst = (uint2*)(g_xnb + (size_t)row * Dd);
    bdst[tid]       = make_uint2(pack2(v0.x, v0.y), pack2(v0.z, v0.w));
    bdst[tid + 256] = make_uint2(pack2(v1.x, v1.y), pack2(v1.z, v1.w));
}

// ---------------- K2: prototype stats ----------------
__global__ void k_prep(const float* __restrict__ proto) {
    int b = blockIdx.x, tid = threadIdx.x;
    const float4* pr = (const float4*)(proto + (size_t)b * Pp);
    float mx = -1e30f, sm = 0.f;
    #pragma unroll 4
    for (int i = tid; i < Pp / 4; i += 256) {
        float4 v = pr[i];
        sm += (v.x + v.y) + (v.z + v.w);
        mx = fmaxf(fmaxf(fmaxf(v.x, v.y), fmaxf(v.z, v.w)), mx);
    }
    __shared__ float rm[256], rs[256];
    rm[tid] = mx; rs[tid] = sm;
    __syncthreads();
    for (int o = 128; o; o >>= 1) {
        if (tid < o) { rm[tid] = fmaxf(rm[tid], rm[tid+o]); rs[tid] += rs[tid+o]; }
        __syncthreads();
    }
    float M = fmaxf(rm[0] * TINV, 21.f), S = rs[0] * TINV;
    __syncthreads();
    float se = 0.f;
    for (int i = tid; i < Pp / 4; i += 256) {
        float4 v = pr[i];
        if (fmaxf(fmaxf(v.x, v.y), fmaxf(v.z, v.w)) * TINV > M - 30.f) {
            se += __expf(v.x*TINV - M) + __expf(v.y*TINV - M)
                + __expf(v.z*TINV - M) + __expf(v.w*TINV - M);
        }
    }
    rs[tid] = se;
    __syncthreads();
    for (int o = 128; o; o >>= 1) {
        if (tid < o) rs[tid] += rs[tid+o];
        __syncthreads();
    }
    if (tid == 0) { g_M[b] = M; g_szp[b] = S; g_sep[b] = rs[0]; }
}

// ---------------- K3: exact fp32 target logit ----------------
__global__ void k_target(const float* __restrict__ F, const int* __restrict__ tg) {
    int b = blockIdx.x, tid = threadIdx.x;
    const float4* f = (const float4*)(F + (size_t)tg[b] * Dd);
    const float4* x = (const float4*)(g_xn + (size_t)b * Dd);
    float d = 0.f;
    for (int i = tid; i < Dd / 4; i += 256) {
        float4 a = x[i], c = f[i];
        d += a.x*c.x + a.y*c.y + a.z*c.z + a.w*c.w;
    }
    #pragma unroll
    for (int o = 16; o; o >>= 1) d += __shfl_xor_sync(~0u, d, o);
    __shared__ float sh[8];
    if ((tid & 31) == 0) sh[tid >> 5] = d;
    __syncthreads();
    if (tid == 0) {
        float t = 0.f;
        #pragma unroll
        for (int i = 0; i < 8; i++) t += sh[i];
        g_zt[b] = t * TINV;
    }
}

// ---------------- K4: 2-CTA/SM GEMM; A via TMA, B via LDG->CVT->STS --------
// CTA tile 128(M) x 128(N), stage k=32, 4 slots of 16 KB (A bf16 + B bf16);
// 128 threads, 4 warps 2mx2n, warp 64x64. B fp32 is LDG'd straight to regs,
// converted, and STS'd as bf16 — its fp32 form never touches smem.
__global__ void __launch_bounds__(128, 2) k_gemm(
    const __grid_constant__ CUtensorMap tmA,
    const float* __restrict__ F) {
    extern __shared__ char dsm[];
    __shared__ __align__(8) uint64_t s_bar[NSTG];   // full[0..3] (A TMA)

    int tid = threadIdx.x, lane = tid & 31, wid = tid >> 5;
    int wm = wid >> 1, wn = wid & 1;
    int m0 = blockIdx.x * BMg;
    int n0 = blockIdx.y * BNg;
    uint32_t sb = (cvs(dsm) + 1023u) & ~1023u;
    uint32_t fullb = cvs(s_bar);

    if (tid == 0) {
        #pragma unroll
        for (int i = 0; i < NSTG; i++) mbar_init(fullb + 8*i, 1);
    }
    __syncthreads();
    if (tid == 0) {
        #pragma unroll
        for (int p = 0; p < NSTG; p++) {
            mbar_expect(fullb + 8*p, A_BY);
            tma2d(sb + p*STG_BY, &tmA, p*KC, m0, fullb + 8*p);
        }
    }

    // ---- B LDG/STS geometry: thread -> (base row tid>>3, float4 col tid&7) --
    int brow = tid >> 3, bcol = tid & 7;
    const float* bsrc = F + (size_t)(n0 + brow) * Dd + (size_t)bcol * 4;
    uint32_t bsts = (uint32_t)bcol * 8u;

    // ---- ldmatrix lane geometry (64-B rows, SW64: X=((r>>1)&3)<<4) ----
    int l15 = lane & 15;
    uint32_t aHi = (uint32_t)(lane >> 4) << 4;
    uint32_t rowAddrA[4], Xa[4];
    #pragma unroll
    for (int mt = 0; mt < 4; mt++) {
        int row = wm*64 + mt*16 + l15;
        rowAddrA[mt] = (uint32_t)row * 64u;
        Xa[mt] = (uint32_t)((row >> 1) & 3) << 4;
    }
    int j = lane >> 3;
    uint32_t bCol = (uint32_t)(j & 1) << 4;
    uint32_t rowAddrB[4], Xb[4];
    #pragma unroll
    for (int u = 0; u < 4; u++) {
        int row = wn*64 + u*16 + (lane & 7) + (j >> 1) * 8;
        rowAddrB[u] = (uint32_t)A_BY + (uint32_t)row * 64u;
        Xb[u] = (uint32_t)((row >> 1) & 3) << 4;
    }

    float c[4][8][4];
    #pragma unroll
    for (int i = 0; i < 4; i++)
        #pragma unroll
        for (int jj = 0; jj < 8; jj++)
            #pragma unroll
            for (int k = 0; k < 4; k++) c[i][jj][k] = 0.f;

    // LDG B fp32 (stage st) -> regs; wait A TMA(st); convert+STS bf16.
    auto stage_b = [&](int st) {
        float4 rb[8];
        const float* src = bsrc + (size_t)st * KC;
        #pragma unroll
        for (int i = 0; i < 8; i++)
            rb[i] = __ldg((const float4*)(src + (size_t)(16 * i) * Dd));
        mbar_wait(fullb + 8*(st & 3), (uint32_t)((st >> 2) & 1));
        uint32_t dst = sb + (uint32_t)(st & 3) * STG_BY + A_BY;
        #pragma unroll
        for (int i = 0; i < 8; i++) {
            int r = brow + 16 * i;
            uint32_t X = (uint32_t)((r >> 1) & 3) << 4;
            asm volatile("st.shared.v2.b32 [%0], {%1,%2};"
                :: "r"(dst + (uint32_t)r * 64u + (bsts ^ X)),
                   "r"(pack2(rb[i].x, rb[i].y)), "r"(pack2(rb[i].z, rb[i].w))
                : "memory");
        }
    };

    // compute stage resident in slot sbase
    auto do_compute = [&](uint32_t sbase) {
        #pragma unroll
        for (int s4 = 0; s4 < 2; s4++) {
            uint32_t kb = (uint32_t)s4 * 32u;
            uint32_t a[4][4], bfr[4][4];
            #pragma unroll
            for (int mt = 0; mt < 4; mt++)
                ldsm4(a[mt][0], a[mt][1], a[mt][2], a[mt][3],
                      sbase + rowAddrA[mt] + ((kb + aHi) ^ Xa[mt]));
            #pragma unroll
            for (int u = 0; u < 4; u++)
                ldsm4(bfr[u][0], bfr[u][1], bfr[u][2], bfr[u][3],
                      sbase + rowAddrB[u] + ((kb + bCol) ^ Xb[u]));
            #pragma unroll
            for (int mt = 0; mt < 4; mt++)
                #pragma unroll
                for (int u = 0; u < 4; u++) {
                    mma16(c[mt][2*u],     a[mt], bfr[u][0], bfr[u][1]);
                    mma16(c[mt][2*u + 1], a[mt], bfr[u][2], bfr[u][3]);
                }
        }
    };

    // ---- prologue: stage 0's B (includes A wait), sync ----
    stage_b(0);
    __syncthreads();

    for (int it = 0; it < NIT; it++) {
        int s = it & 3;
        uint32_t sbase = sb + (uint32_t)s * STG_BY;

        do_compute(sbase);              // fills tensor queue

        if (it + 1 < NIT) stage_b(it + 1);   // LDG latency hides under drain

        // single barrier: compute(s) reads done + stage_b(it+1) writes visible
        __syncthreads();

        // refill A slot s with stage it+4
        if (tid == 0 && it + NSTG < NIT) {
            mbar_expect(fullb + 8*s, A_BY);
            tma2d(sbase, &tmA, (it + NSTG) * KC, m0, fullb + 8*s);
        }
    }
    __syncthreads();

    // ---- fused epilogue: per-row sum + softmax numerator partials ----
    int g = lane >> 2, q = lane & 3;
    float* redv = (float*)dsm;          // [2 wn][128 rows]
    float* rede = redv + 256;
    #pragma unroll
    for (int mt = 0; mt < 4; mt++) {
        int r0 = wm*64 + mt*16 + g;
        float M0 = g_M[m0 + r0], M1 = g_M[m0 + r0 + 8];
        float sv0 = 0.f, se0 = 0.f, sv1 = 0.f, se1 = 0.f;
        #pragma unroll
        for (int nt = 0; nt < 8; nt++) {
            float v;
            v = c[mt][nt][0]; sv0 += v; se0 += __expf(fmaf(TINV, v, -M0));
            v = c[mt][nt][1]; sv0 += v; se0 += __expf(fmaf(TINV, v, -M0));
            v = c[mt][nt][2]; sv1 += v; se1 += __expf(fmaf(TINV, v, -M1));
            v = c[mt][nt][3]; sv1 += v; se1 += __expf(fmaf(TINV, v, -M1));
        }
        #pragma unroll
        for (int o = 1; o <= 2; o <<= 1) {
            sv0 += __shfl_xor_sync(~0u, sv0, o);
            se0 += __shfl_xor_sync(~0u, se0, o);
            sv1 += __shfl_xor_sync(~0u, sv1, o);
            se1 += __shfl_xor_sync(~0u, se1, o);
        }
        if (q == 0) {
            redv[wn*128 + r0]     = sv0; rede[wn*128 + r0]     = se0;
            redv[wn*128 + r0 + 8] = sv1; rede[wn*128 + r0 + 8] = se1;
        }
    }
    __syncthreads();
    {
        float sv = redv[tid] + redv[128 + tid];
        float se = rede[tid] + rede[128 + tid];
        g_psv[(size_t)(m0 + tid) * NBLK + blockIdx.y] = sv;
        g_pse[(size_t)(m0 + tid) * NBLK + blockIdx.y] = se;
    }
}

// ---------------- K5: per-row combine over 512 N-block partials ------------
__global__ void k_finalrow(void) {
    int b = blockIdx.x, tid = threadIdx.x;
    float sv = g_psv[(size_t)b * NBLK + tid] + g_psv[(size_t)b * NBLK + tid + 256];
    float se = g_pse[(size_t)b * NBLK + tid] + g_pse[(size_t)b * NBLK + tid + 256];
    __shared__ float rv[256], re[256];
    rv[tid] = sv; re[tid] = se;
    __syncthreads();
    for (int o = 128; o; o >>= 1) {
        if (tid < o) { rv[tid] += rv[tid+o]; re[tid] += re[tid+o]; }
        __syncthreads();
    }
    if (tid == 0) {
        float M = g_M[b];
        float lse = M + logf(g_sep[b] + re[0]);
        float T = g_szp[b] + TINV * rv[0];
        g_rowloss[b] = lse - (1.f - EPS_) * g_zt[b] - EPS_ * (T / (float)CTOT);
    }
}

// ---------------- K6: mean ----------------
__global__ void k_final(float* __restrict__ out) {
    int tid = threadIdx.x;
    float v = g_rowloss[tid];
    #pragma unroll
    for (int o = 16; o; o >>= 1) v += __shfl_xor_sync(~0u, v, o);
    __shared__ float sh[8];
    if ((tid & 31) == 0) sh[tid >> 5] = v;
    __syncthreads();
    if (tid == 0) {
        float s = 0.f;
        #pragma unroll
        for (int i = 0; i < 8; i++) s += sh[i];
        out[0] = s / (float)Bb;
    }
}

// ---------------------------------------------------------------------------
typedef CUresult (*PFN_tmapenc)(
    CUtensorMap*, CUtensorMapDataType, cuuint32_t, void*,
    const cuuint64_t*, const cuuint64_t*, const cuuint32_t*, const cuuint32_t*,
    CUtensorMapInterleave, CUtensorMapSwizzle, CUtensorMapL2promotion,
    CUtensorMapFloatOOBfill);

extern "C" void kernel_launch(void* const* d_in, const int* in_sizes, int n_in,
                              void* d_out, int out_size) {
    const float* inputs    = (const float*)d_in[0];
    const int*   targets   = (const int*)  d_in[1];
    const float* prototype = (const float*)d_in[2];
    const float* features  = (const float*)d_in[3];
    float* out = (float*)d_out;

    cudaFuncSetAttribute(k_gemm, cudaFuncAttributeMaxDynamicSharedMemorySize,
                         SMEM_DYN);

    PFN_tmapenc enc = nullptr;
    cudaDriverEntryPointQueryResult qr;
    cudaGetDriverEntryPointByVersion("cuTensorMapEncodeTiled", (void**)&enc,
                                     12000, cudaEnableDefault, &qr);

    void* xnbp = nullptr;
    cudaGetSymbolAddress(&xnbp, g_xnb);

    CUtensorMap tmA;
    {
        cuuint64_t dims[2]    = {Dd, Bb};
        cuuint64_t strides[1] = {Dd * 2ull};
        cuuint32_t box[2]     = {KC, BMg};         // 32 bf16 = 64 B x 128 rows
        cuuint32_t es[2]      = {1, 1};
        enc(&tmA, CU_TENSOR_MAP_DATA_TYPE_BFLOAT16, 2, xnbp, dims, strides, box, es,
            CU_TENSOR_MAP_INTERLEAVE_NONE, CU_TENSOR_MAP_SWIZZLE_64B,
            CU_TENSOR_MAP_L2_PROMOTION_L2_128B, CU_TENSOR_MAP_FLOAT_OOB_FILL_NONE);
    }

    k_normalize<<<Bb, 256>>>(inputs);
    k_prep<<<Bb, 256>>>(prototype);
    k_target<<<Bb, 256>>>(features, targets);
    dim3 grid(2, NBLK);
    k_gemm<<<grid, 128, SMEM_DYN>>>(tmA, features);
    k_finalrow<<<Bb, 256>>>();
    k_final<<<1, 256>>>(out);
}

// round 14
// speedup vs baseline: 1.4479x; 1.4479x over previous
#include <cuda_runtime.h>
#include <cuda.h>
#include <cuda_bf16.h>
#include <math.h>
#include <stdint.h>

#define Bb 256
#define Dd 2048
#define Nn 65536
#define Pp 4096
#define CTOT (Pp + Nn)
#define TINV 20.0f
#define EPS_ 0.1f

#define BMg 128                  // M rows per CTA
#define BNg 128                  // N cols per CTA
#define NBLK (Nn / BNg)          // 512 N-blocks
#define KC 32                    // K elems per stage
#define NIT (Dd / KC)            // 64 stages
#define NSTG 3
#define A_BY 8192                // A bf16 slot: 128 rows x 64 B (SW64)
#define F_BY 16384               // B fp32 slot: 128 rows x 128 B (SW128)
#define G_BY 8192                // B bf16 slot: 128 rows x 64 B
#define A_BASE 0
#define F_BASE (NSTG * A_BY)             // 24576
#define G_BASE (F_BASE + NSTG * F_BY)    // 73728
#define SMEM_DYN (G_BASE + NSTG * G_BY + 1024)   // 99328

__device__ __align__(128) float g_xn[Bb * Dd];
__device__ __align__(128) __nv_bfloat16 g_xnb[Bb * Dd];
__device__ float g_M[Bb], g_szp[Bb], g_sep[Bb], g_zt[Bb], g_rowloss[Bb];
__device__ float g_psv[Bb * NBLK], g_pse[Bb * NBLK];

// ---------------- PTX helpers ----------------
__device__ __forceinline__ uint32_t cvs(const void* p) {
    return (uint32_t)__cvta_generic_to_shared(p);
}
__device__ __forceinline__ void mbar_init(uint32_t a, uint32_t c) {
    asm volatile("mbarrier.init.shared.b64 [%0], %1;" :: "r"(a), "r"(c) : "memory");
}
__device__ __forceinline__ void mbar_expect(uint32_t a, uint32_t tx) {
    asm volatile("mbarrier.arrive.expect_tx.shared.b64 _, [%0], %1;"
                 :: "r"(a), "r"(tx) : "memory");
}
__device__ __forceinline__ void mbar_arrive(uint32_t a) {
    asm volatile("mbarrier.arrive.shared.b64 _, [%0];" :: "r"(a) : "memory");
}
__device__ __forceinline__ void mbar_wait(uint32_t a, uint32_t ph) {
    asm volatile(
        "{\n\t.reg .pred P;\n\t"
        "W_%=:\n\t"
        "mbarrier.try_wait.parity.acquire.cta.shared::cta.b64 P, [%0], %1, 0x989680;\n\t"
        "@P bra D_%=;\n\t"
        "bra.uni W_%=;\n\t"
        "D_%=:\n\t}"
        :: "r"(a), "r"(ph) : "memory");
}
__device__ __forceinline__ void tma2d(uint32_t dst, const CUtensorMap* m,
                                      int x, int y, uint32_t bar) {
    asm volatile(
        "cp.async.bulk.tensor.2d.shared::cta.global.tile.mbarrier::complete_tx::bytes "
        "[%0], [%1, {%2, %3}], [%4];"
        :: "r"(dst), "l"(m), "r"(x), "r"(y), "r"(bar) : "memory");
}
__device__ __forceinline__ void ldsm4(uint32_t& r0, uint32_t& r1, uint32_t& r2,
                                      uint32_t& r3, uint32_t addr) {
    asm volatile(
        "ldmatrix.sync.aligned.m8n8.x4.shared.b16 {%0,%1,%2,%3}, [%4];"
        : "=r"(r0), "=r"(r1), "=r"(r2), "=r"(r3) : "r"(addr));
}
__device__ __forceinline__ void mma16(float c[4], const uint32_t a[4],
                                      uint32_t b0, uint32_t b1) {
    asm("mma.sync.aligned.m16n8k16.row.col.f32.bf16.bf16.f32 "
        "{%0,%1,%2,%3},{%4,%5,%6,%7},{%8,%9},{%0,%1,%2,%3};"
        : "+f"(c[0]), "+f"(c[1]), "+f"(c[2]), "+f"(c[3])
        : "r"(a[0]), "r"(a[1]), "r"(a[2]), "r"(a[3]), "r"(b0), "r"(b1));
}
__device__ __forceinline__ uint32_t pack2(float a, float b) {
    __nv_bfloat162 p = __floats2bfloat162_rn(a, b);
    return *(uint32_t*)&p;
}

// ---------------- K1: normalize inputs (fp32 + bf16 out) ----------------
__global__ void k_normalize(const float* __restrict__ in) {
    int row = blockIdx.x, tid = threadIdx.x;
    const float4* src = (const float4*)(in + (size_t)row * Dd);
    float4 v0 = src[tid], v1 = src[tid + 256];
    float ss = v0.x*v0.x + v0.y*v0.y + v0.z*v0.z + v0.w*v0.w
             + v1.x*v1.x + v1.y*v1.y + v1.z*v1.z + v1.w*v1.w;
    #pragma unroll
    for (int o = 16; o; o >>= 1) ss += __shfl_xor_sync(~0u, ss, o);
    __shared__ float sh[8];
    if ((tid & 31) == 0) sh[tid >> 5] = ss;
    __syncthreads();
    if (tid == 0) {
        float t = 0.f;
        #pragma unroll
        for (int i = 0; i < 8; i++) t += sh[i];
        sh[0] = rsqrtf(t);
    }
    __syncthreads();
    float iv = sh[0];
    v0.x*=iv; v0.y*=iv; v0.z*=iv; v0.w*=iv;
    v1.x*=iv; v1.y*=iv; v1.z*=iv; v1.w*=iv;
    float4* dst = (float4*)(g_xn + (size_t)row * Dd);
    dst[tid] = v0; dst[tid + 256] = v1;
    uint2* bdst = (uint2*)(g_xnb + (size_t)row * Dd);
    bdst[tid]       = make_uint2(pack2(v0.x, v0.y), pack2(v0.z, v0.w));
    bdst[tid + 256] = make_uint2(pack2(v1.x, v1.y), pack2(v1.z, v1.w));
}

// ---------------- K2: prototype stats ----------------
__global__ void k_prep(const float* __restrict__ proto) {
    int b = blockIdx.x, tid = threadIdx.x;
    const float4* pr = (const float4*)(proto + (size_t)b * Pp);
    float mx = -1e30f, sm = 0.f;
    #pragma unroll 4
    for (int i = tid; i < Pp / 4; i += 256) {
        float4 v = pr[i];
        sm += (v.x + v.y) + (v.z + v.w);
        mx = fmaxf(fmaxf(fmaxf(v.x, v.y), fmaxf(v.z, v.w)), mx);
    }
    __shared__ float rm[256], rs[256];
    rm[tid] = mx; rs[tid] = sm;
    __syncthreads();
    for (int o = 128; o; o >>= 1) {
        if (tid < o) { rm[tid] = fmaxf(rm[tid], rm[tid+o]); rs[tid] += rs[tid+o]; }
        __syncthreads();
    }
    float M = fmaxf(rm[0] * TINV, 21.f), S = rs[0] * TINV;
    __syncthreads();
    float se = 0.f;
    for (int i = tid; i < Pp / 4; i += 256) {
        float4 v = pr[i];
        if (fmaxf(fmaxf(v.x, v.y), fmaxf(v.z, v.w)) * TINV > M - 30.f) {
            se += __expf(v.x*TINV - M) + __expf(v.y*TINV - M)
                + __expf(v.z*TINV - M) + __expf(v.w*TINV - M);
        }
    }
    rs[tid] = se;
    __syncthreads();
    for (int o = 128; o; o >>= 1) {
        if (tid < o) rs[tid] += rs[tid+o];
        __syncthreads();
    }
    if (tid == 0) { g_M[b] = M; g_szp[b] = S; g_sep[b] = rs[0]; }
}

// ---------------- K3: exact fp32 target logit ----------------
__global__ void k_target(const float* __restrict__ F, const int* __restrict__ tg) {
    int b = blockIdx.x, tid = threadIdx.x;
    const float4* f = (const float4*)(F + (size_t)tg[b] * Dd);
    const float4* x = (const float4*)(g_xn + (size_t)b * Dd);
    float d = 0.f;
    for (int i = tid; i < Dd / 4; i += 256) {
        float4 a = x[i], c = f[i];
        d += a.x*c.x + a.y*c.y + a.z*c.z + a.w*c.w;
    }
    #pragma unroll
    for (int o = 16; o; o >>= 1) d += __shfl_xor_sync(~0u, d, o);
    __shared__ float sh[8];
    if ((tid & 31) == 0) sh[tid >> 5] = d;
    __syncthreads();
    if (tid == 0) {
        float t = 0.f;
        #pragma unroll
        for (int i = 0; i < 8; i++) t += sh[i];
        g_zt[b] = t * TINV;
    }
}

// ---------------- K4: warp-specialized GEMM (4 compute + 1 producer warp) ---
// CTA tile 128x128, k=32 stages, 3-slot rings: A(TMA), Bf32(TMA), Bbf16(conv).
// No __syncthreads in the main loop — mbarrier producer/consumer only.
__global__ void __launch_bounds__(160, 2) k_gemm(
    const __grid_constant__ CUtensorMap tmA,
    const __grid_constant__ CUtensorMap tmB) {
    extern __shared__ char dsm[];
    __shared__ __align__(8) uint64_t s_bar[4 * NSTG]; // tmafA, tmafF, bf16f, empt

    int tid = threadIdx.x, lane = tid & 31, wid = tid >> 5;
    int m0 = blockIdx.x * BMg;
    int n0 = blockIdx.y * BNg;
    uint32_t sb = (cvs(dsm) + 1023u) & ~1023u;
    uint32_t tmafA = cvs(s_bar);
    uint32_t tmafF = tmafA + 8 * NSTG;
    uint32_t bf16f = tmafF + 8 * NSTG;
    uint32_t emptb = bf16f + 8 * NSTG;

    if (tid == 0) {
        #pragma unroll
        for (int i = 0; i < NSTG; i++) {
            mbar_init(tmafA + 8*i, 1);
            mbar_init(tmafF + 8*i, 1);
            mbar_init(bf16f + 8*i, 1);
            mbar_init(emptb + 8*i, 4);
        }
    }
    __syncthreads();

    if (wid == 4) {
        // =================== PRODUCER WARP ===================
        // prologue: issue Bf32 TMA for stages 0..2
        if (lane == 0) {
            #pragma unroll
            for (int p = 0; p < NSTG; p++) {
                mbar_expect(tmafF + 8*p, F_BY);
                tma2d(sb + F_BASE + p*F_BY, &tmB, p*KC, n0, tmafF + 8*p);
            }
        }
        // convert geometry: 4 rows per lane
        uint32_t XcL[4], Xc6L[4], fs[4], gs[4];
        #pragma unroll
        for (int i = 0; i < 4; i++) {
            int r = lane + 32*i;
            XcL[i]  = (uint32_t)(r & 7) << 4;
            Xc6L[i] = (uint32_t)((r >> 1) & 3) << 4;
            fs[i] = (uint32_t)r * 128u;
            gs[i] = (uint32_t)r * 64u;
        }

        for (int st = 0; st < NIT; st++) {
            int j = st % NSTG;
            uint32_t k = (uint32_t)(st / NSTG);
            if (st >= NSTG) mbar_wait(emptb + 8*j, (k - 1) & 1);
            if (lane == 0) {
                mbar_expect(tmafA + 8*j, A_BY);
                tma2d(sb + A_BASE + j*A_BY, &tmA, st*KC, m0, tmafA + 8*j);
            }
            mbar_wait(tmafF + 8*j, k & 1);
            // convert Bf32[j] -> Bbf16[j]
            uint32_t fb = sb + F_BASE + (uint32_t)j * F_BY;
            uint32_t gb = sb + G_BASE + (uint32_t)j * G_BY;
            #pragma unroll
            for (int i = 0; i < 4; i++) {
                uint32_t srcb = fb + fs[i], dstb = gb + gs[i];
                float4 f0, f1, f2, f3, f4, f5, f6, f7;
                asm volatile("ld.shared.v4.f32 {%0,%1,%2,%3}, [%4];"
                    : "=f"(f0.x), "=f"(f0.y), "=f"(f0.z), "=f"(f0.w)
                    : "r"(srcb + (0u ^ XcL[i])));
                asm volatile("ld.shared.v4.f32 {%0,%1,%2,%3}, [%4];"
                    : "=f"(f1.x), "=f"(f1.y), "=f"(f1.z), "=f"(f1.w)
                    : "r"(srcb + (16u ^ XcL[i])));
                asm volatile("ld.shared.v4.f32 {%0,%1,%2,%3}, [%4];"
                    : "=f"(f2.x), "=f"(f2.y), "=f"(f2.z), "=f"(f2.w)
                    : "r"(srcb + (32u ^ XcL[i])));
                asm volatile("ld.shared.v4.f32 {%0,%1,%2,%3}, [%4];"
                    : "=f"(f3.x), "=f"(f3.y), "=f"(f3.z), "=f"(f3.w)
                    : "r"(srcb + (48u ^ XcL[i])));
                asm volatile("ld.shared.v4.f32 {%0,%1,%2,%3}, [%4];"
                    : "=f"(f4.x), "=f"(f4.y), "=f"(f4.z), "=f"(f4.w)
                    : "r"(srcb + (64u ^ XcL[i])));
                asm volatile("ld.shared.v4.f32 {%0,%1,%2,%3}, [%4];"
                    : "=f"(f5.x), "=f"(f5.y), "=f"(f5.z), "=f"(f5.w)
                    : "r"(srcb + (80u ^ XcL[i])));
                asm volatile("ld.shared.v4.f32 {%0,%1,%2,%3}, [%4];"
                    : "=f"(f6.x), "=f"(f6.y), "=f"(f6.z), "=f"(f6.w)
                    : "r"(srcb + (96u ^ XcL[i])));
                asm volatile("ld.shared.v4.f32 {%0,%1,%2,%3}, [%4];"
                    : "=f"(f7.x), "=f"(f7.y), "=f"(f7.z), "=f"(f7.w)
                    : "r"(srcb + (112u ^ XcL[i])));
                asm volatile("st.shared.v4.b32 [%0], {%1,%2,%3,%4};"
                    :: "r"(dstb + (0u ^ Xc6L[i])),
                       "r"(pack2(f0.x, f0.y)), "r"(pack2(f0.z, f0.w)),
                       "r"(pack2(f1.x, f1.y)), "r"(pack2(f1.z, f1.w)) : "memory");
                asm volatile("st.shared.v4.b32 [%0], {%1,%2,%3,%4};"
                    :: "r"(dstb + (16u ^ Xc6L[i])),
                       "r"(pack2(f2.x, f2.y)), "r"(pack2(f2.z, f2.w)),
                       "r"(pack2(f3.x, f3.y)), "r"(pack2(f3.z, f3.w)) : "memory");
                asm volatile("st.shared.v4.b32 [%0], {%1,%2,%3,%4};"
                    :: "r"(dstb + (32u ^ Xc6L[i])),
                       "r"(pack2(f4.x, f4.y)), "r"(pack2(f4.z, f4.w)),
                       "r"(pack2(f5.x, f5.y)), "r"(pack2(f5.z, f5.w)) : "memory");
                asm volatile("st.shared.v4.b32 [%0], {%1,%2,%3,%4};"
                    :: "r"(dstb + (48u ^ Xc6L[i])),
                       "r"(pack2(f6.x, f6.y)), "r"(pack2(f6.z, f6.w)),
                       "r"(pack2(f7.x, f7.y)), "r"(pack2(f7.z, f7.w)) : "memory");
            }
            __syncwarp();
            if (lane == 0) {
                mbar_arrive(bf16f + 8*j);
                if (st + NSTG < NIT) {
                    mbar_expect(tmafF + 8*j, F_BY);
                    tma2d(sb + F_BASE + j*F_BY, &tmB, (st + NSTG)*KC, n0,
                          tmafF + 8*j);
                }
            }
        }
    } else {
        // =================== COMPUTE WARPS (0-3) ===================
        int wm = wid >> 1, wn = wid & 1;
        int l15 = lane & 15;
        uint32_t aHi = (uint32_t)(lane >> 4) << 4;
        uint32_t rowAddrA[4], Xa[4];
        #pragma unroll
        for (int mt = 0; mt < 4; mt++) {
            int row = wm*64 + mt*16 + l15;
            rowAddrA[mt] = (uint32_t)row * 64u;
            Xa[mt] = (uint32_t)((row >> 1) & 3) << 4;
        }
        int j4 = lane >> 3;
        uint32_t bCol = (uint32_t)(j4 & 1) << 4;
        uint32_t rowAddrB[4], Xb[4];
        #pragma unroll
        for (int u = 0; u < 4; u++) {
            int row = wn*64 + u*16 + (lane & 7) + (j4 >> 1) * 8;
            rowAddrB[u] = (uint32_t)row * 64u;
            Xb[u] = (uint32_t)((row >> 1) & 3) << 4;
        }

        float c[4][8][4];
        #pragma unroll
        for (int i = 0; i < 4; i++)
            #pragma unroll
            for (int jj = 0; jj < 8; jj++)
                #pragma unroll
                for (int kk = 0; kk < 4; kk++) c[i][jj][kk] = 0.f;

        for (int it = 0; it < NIT; it++) {
            int j = it % NSTG;
            uint32_t k = (uint32_t)(it / NSTG);
            mbar_wait(bf16f + 8*j, k & 1);
            mbar_wait(tmafA + 8*j, k & 1);
            uint32_t aBase = sb + A_BASE + (uint32_t)j * A_BY;
            uint32_t gBase = sb + G_BASE + (uint32_t)j * G_BY;
            #pragma unroll
            for (int s4 = 0; s4 < 2; s4++) {
                uint32_t kb = (uint32_t)s4 * 32u;
                uint32_t a[4][4], bfr[4][4];
                #pragma unroll
                for (int mt = 0; mt < 4; mt++)
                    ldsm4(a[mt][0], a[mt][1], a[mt][2], a[mt][3],
                          aBase + rowAddrA[mt] + ((kb + aHi) ^ Xa[mt]));
                #pragma unroll
                for (int u = 0; u < 4; u++)
                    ldsm4(bfr[u][0], bfr[u][1], bfr[u][2], bfr[u][3],
                          gBase + rowAddrB[u] + ((kb + bCol) ^ Xb[u]));
                #pragma unroll
                for (int mt = 0; mt < 4; mt++)
                    #pragma unroll
                    for (int u = 0; u < 4; u++) {
                        mma16(c[mt][2*u],     a[mt], bfr[u][0], bfr[u][1]);
                        mma16(c[mt][2*u + 1], a[mt], bfr[u][2], bfr[u][3]);
                    }
            }
            __syncwarp();
            if (lane == 0) mbar_arrive(emptb + 8*j);
        }

        // stash accumulators path continues after the block-wide sync below
        __syncthreads();

        // ---- fused epilogue: per-row sum + softmax numerator partials ----
        int g = lane >> 2, q = lane & 3;
        float* redv = (float*)dsm;          // [2 wn][128 rows]
        float* rede = redv + 256;
        #pragma unroll
        for (int mt = 0; mt < 4; mt++) {
            int r0 = wm*64 + mt*16 + g;
            float M0 = g_M[m0 + r0], M1 = g_M[m0 + r0 + 8];
            float sv0 = 0.f, se0 = 0.f, sv1 = 0.f, se1 = 0.f;
            #pragma unroll
            for (int nt = 0; nt < 8; nt++) {
                float v;
                v = c[mt][nt][0]; sv0 += v; se0 += __expf(fmaf(TINV, v, -M0));
                v = c[mt][nt][1]; sv0 += v; se0 += __expf(fmaf(TINV, v, -M0));
                v = c[mt][nt][2]; sv1 += v; se1 += __expf(fmaf(TINV, v, -M1));
                v = c[mt][nt][3]; sv1 += v; se1 += __expf(fmaf(TINV, v, -M1));
            }
            #pragma unroll
            for (int o = 1; o <= 2; o <<= 1) {
                sv0 += __shfl_xor_sync(~0u, sv0, o);
                se0 += __shfl_xor_sync(~0u, se0, o);
                sv1 += __shfl_xor_sync(~0u, sv1, o);
                se1 += __shfl_xor_sync(~0u, se1, o);
            }
            if (q == 0) {
                redv[wn*128 + r0]     = sv0; rede[wn*128 + r0]     = se0;
                redv[wn*128 + r0 + 8] = sv1; rede[wn*128 + r0 + 8] = se1;
            }
        }
    }
    if (wid == 4) __syncthreads();   // producer joins the epilogue sync
    __syncthreads();
    if (tid < 128) {
        float* redv = (float*)dsm;
        float* rede = redv + 256;
        float sv = redv[tid] + redv[128 + tid];
        float se = rede[tid] + rede[128 + tid];
        g_psv[(size_t)(m0 + tid) * NBLK + blockIdx.y] = sv;
        g_pse[(size_t)(m0 + tid) * NBLK + blockIdx.y] = se;
    }
}

// ---------------- K5: per-row combine over 512 N-block partials ------------
__global__ void k_finalrow(void) {
    int b = blockIdx.x, tid = threadIdx.x;
    float sv = g_psv[(size_t)b * NBLK + tid] + g_psv[(size_t)b * NBLK + tid + 256];
    float se = g_pse[(size_t)b * NBLK + tid] + g_pse[(size_t)b * NBLK + tid + 256];
    __shared__ float rv[256], re[256];
    rv[tid] = sv; re[tid] = se;
    __syncthreads();
    for (int o = 128; o; o >>= 1) {
        if (tid < o) { rv[tid] += rv[tid+o]; re[tid] += re[tid+o]; }
        __syncthreads();
    }
    if (tid == 0) {
        float M = g_M[b];
        float lse = M + logf(g_sep[b] + re[0]);
        float T = g_szp[b] + TINV * rv[0];
        g_rowloss[b] = lse - (1.f - EPS_) * g_zt[b] - EPS_ * (T / (float)CTOT);
    }
}

// ---------------- K6: mean ----------------
__global__ void k_final(float* __restrict__ out) {
    int tid = threadIdx.x;
    float v = g_rowloss[tid];
    #pragma unroll
    for (int o = 16; o; o >>= 1) v += __shfl_xor_sync(~0u, v, o);
    __shared__ float sh[8];
    if ((tid & 31) == 0) sh[tid >> 5] = v;
    __syncthreads();
    if (tid == 0) {
        float s = 0.f;
        #pragma unroll
        for (int i = 0; i < 8; i++) s += sh[i];
        out[0] = s / (float)Bb;
    }
}

// ---------------------------------------------------------------------------
typedef CUresult (*PFN_tmapenc)(
    CUtensorMap*, CUtensorMapDataType, cuuint32_t, void*,
    const cuuint64_t*, const cuuint64_t*, const cuuint32_t*, const cuuint32_t*,
    CUtensorMapInterleave, CUtensorMapSwizzle, CUtensorMapL2promotion,
    CUtensorMapFloatOOBfill);

extern "C" void kernel_launch(void* const* d_in, const int* in_sizes, int n_in,
                              void* d_out, int out_size) {
    const float* inputs    = (const float*)d_in[0];
    const int*   targets   = (const int*)  d_in[1];
    const float* prototype = (const float*)d_in[2];
    const float* features  = (const float*)d_in[3];
    float* out = (float*)d_out;

    cudaFuncSetAttribute(k_gemm, cudaFuncAttributeMaxDynamicSharedMemorySize,
                         SMEM_DYN);

    PFN_tmapenc enc = nullptr;
    cudaDriverEntryPointQueryResult qr;
    cudaGetDriverEntryPointByVersion("cuTensorMapEncodeTiled", (void**)&enc,
                                     12000, cudaEnableDefault, &qr);

    void* xnbp = nullptr;
    cudaGetSymbolAddress(&xnbp, g_xnb);

    CUtensorMap tmA, tmB;
    {
        cuuint64_t dims[2]    = {Dd, Bb};
        cuuint64_t strides[1] = {Dd * 2ull};
        cuuint32_t box[2]     = {KC, BMg};         // 32 bf16 = 64 B x 128 rows
        cuuint32_t es[2]      = {1, 1};
        enc(&tmA, CU_TENSOR_MAP_DATA_TYPE_BFLOAT16, 2, xnbp, dims, strides, box, es,
            CU_TENSOR_MAP_INTERLEAVE_NONE, CU_TENSOR_MAP_SWIZZLE_64B,
            CU_TENSOR_MAP_L2_PROMOTION_L2_128B, CU_TENSOR_MAP_FLOAT_OOB_FILL_NONE);
    }
    {
        cuuint64_t dims[2]    = {Dd, Nn};
        cuuint64_t strides[1] = {Dd * 4ull};
        cuuint32_t box[2]     = {KC, BNg};         // 32 f32 = 128 B x 128 rows
        cuuint32_t es[2]      = {1, 1};
        enc(&tmB, CU_TENSOR_MAP_DATA_TYPE_FLOAT32, 2, (void*)features,
            dims, strides, box, es,
            CU_TENSOR_MAP_INTERLEAVE_NONE, CU_TENSOR_MAP_SWIZZLE_128B,
            CU_TENSOR_MAP_L2_PROMOTION_L2_128B, CU_TENSOR_MAP_FLOAT_OOB_FILL_NONE);
    }

    k_normalize<<<Bb, 256>>>(inputs);
    k_prep<<<Bb, 256>>>(prototype);
    k_target<<<Bb, 256>>>(features, targets);
    dim3 grid(2, NBLK);
    k_gemm<<<grid, 160, SMEM_DYN>>>(tmA, tmB);
    k_finalrow<<<Bb, 256>>>();
    k_final<<<1, 256>>>(out);
}